// round 5
// baseline (speedup 1.0000x reference)
#include <cuda_runtime.h>

// RelateBatch: one-hot block structure of batch_object_map (obj_q = n//8)
// collapses both einsum chains to per-8x8 diagonal-block row/col reductions.
// Reads 8.4 MB instead of 537 MB.
// Round 5: lane-per-row layout. Each lane loads one full 256B row slice
// (16 independent LDG.128, MLP=16), row reduction is thread-local, col
// reduction is a 3-stage butterfly in the 8-lane group. 1024 warps total;
// whole payload fits in flight.

#define EPSF 1e-12f

__device__ __forceinline__ float pnotf(float x, float a) {
    // a * log(max(1 - exp(min(x,0)), EPS)) + (1-a) * x
    float xm = fminf(x, 0.0f);
    float e  = __expf(xm);
    float l  = __logf(fmaxf(1.0f - e, EPSF));
    return fmaf(a, l, (1.0f - a) * x);
}

__global__ __launch_bounds__(32) void relate_batch_kernel(
    const float* __restrict__ log_prior,   // (64, 2, 512)
    const float* __restrict__ loglik,      // (64, 512, 512, 8)
    const float* __restrict__ quant,       // (64, 2)
    float* __restrict__ out)               // (64, 2, 512)
{
    constexpr unsigned N = 512;
    const unsigned p    = blockIdx.y;                    // 0..63
    const unsigned lane = threadIdx.x;                   // 0..31
    const unsigned tq   = lane >> 3;                     // tile-quarter 0..3
    const unsigned r    = lane & 7u;                     // row within tile
    const unsigned g    = blockIdx.x * 4u + tq;          // 0..63 (tile)
    const unsigned n    = g * 8u + r;                    // row object

    // Row slice: loglik[p, n, g*8 .. g*8+7, 0..7] = 64 contiguous floats.
    const unsigned base = ((p * N + n) * N + g * 8u) * 8u;
    const float4* src = reinterpret_cast<const float4*>(loglik + base);
    float4 d[16];
    #pragma unroll
    for (int k = 0; k < 16; k++) d[k] = __ldcs(src + k);

    const float q0 = quant[2u * p + 0u];
    const float q1 = quant[2u * p + 1u];
    const float lp0_n = log_prior[(p * 2u + 0u) * N + n];
    // lp1 for the whole tile: 8 contiguous floats.
    const float4* lp1p =
        reinterpret_cast<const float4*>(log_prior + (p * 2u + 1u) * N + g * 8u);
    float4 l0 = __ldg(lp1p);
    float4 l1 = __ldg(lp1p + 1);
    float lp1[8] = {l0.x, l0.y, l0.z, l0.w, l1.x, l1.y, l1.z, l1.w};

    // ll[m] = min(mean_f, 0)
    float ll[8];
    #pragma unroll
    for (int m = 0; m < 8; m++) {
        float4 u = d[2 * m], v = d[2 * m + 1];
        float s = ((u.x + u.y) + (u.z + u.w)) + ((v.x + v.y) + (v.z + v.w));
        ll[m] = fminf(s * 0.125f, 0.0f);
    }

    // Row path (out0): thread-local sum of pnot(ll+lp1[m], q1), skip diagonal.
    // Col path (out1): w[m] = pnot(ll+lp0_n, q0), summed over r via butterfly.
    float rs = 0.0f;
    float w[8];
    #pragma unroll
    for (int m = 0; m < 8; m++) {
        float dm = ((unsigned)m == r) ? 0.0f : 1.0f;
        rs   += dm * pnotf(ll[m] + lp1[m], q1);
        w[m]  = dm * pnotf(ll[m] + lp0_n, q0);
    }

    out[(p * 2u + 0u) * N + n] = pnotf(rs, q1) + lp0_n;

    // Butterfly over the 8-lane row group: all lanes end with full col sums.
    #pragma unroll
    for (int dd = 1; dd < 8; dd <<= 1) {
        #pragma unroll
        for (int m = 0; m < 8; m++)
            w[m] += __shfl_xor_sync(0xffffffffu, w[m], dd);
    }

    // Lane r emits column m = r.
    float cs = w[0], lpr = lp1[0];
    #pragma unroll
    for (int m = 1; m < 8; m++) {
        cs  = (r == (unsigned)m) ? w[m]   : cs;
        lpr = (r == (unsigned)m) ? lp1[m] : lpr;
    }
    out[(p * 2u + 1u) * N + g * 8u + r] = pnotf(cs, q0) + lpr;
}

extern "C" void kernel_launch(void* const* d_in, const int* in_sizes, int n_in,
                              void* d_out, int out_size) {
    const float* log_prior = (const float*)d_in[0];   // (64,2,512)
    const float* loglik    = (const float*)d_in[1];   // (64,512,512,8)
    const float* quant     = (const float*)d_in[2];   // (64,2)
    float* out = (float*)d_out;                       // (64,2,512)

    dim3 grid(16, 64);   // 16 tile-quads x 64 batches = 1024 single-warp blocks
    dim3 block(32);
    relate_batch_kernel<<<grid, block>>>(log_prior, loglik, quant, out);
}